// round 11
// baseline (speedup 1.0000x reference)
#include <cuda_runtime.h>
#include <cuda_bf16.h>
#include <cstdint>
#include <math.h>

#define BATCH 2
#define MPERB 65536
#define MTOT  131072
#define EDIM  512
#define TOPK  256
#define S3    16
#define K3M   4096
#define TROW  80

// k1 smem: B (W hi/lo) 3 stages, then A (x split) 2 stages
#define K1_BSTG 40960
#define K1_A0   (3 * K1_BSTG)            // 122880
#define K1_ASTG 20480
#define SMEM1   (K1_A0 + 2 * K1_ASTG)    // 163840

// k3 smem: A (probs hi/lo, 128 k-rows) 3 stages, then B (x split, 256 e-rows) 2 stages
#define K3_ASTG 20480                    // 128 * 80 * 2
#define K3_B0   (3 * K3_ASTG)            // 61440
#define K3_BSTG 40960                    // 256 * 80 * 2
#define SMEM3   (K3_B0 + 2 * K3_BSTG)    // 143360

// ---------------- scratch ----------------
__device__ __nv_bfloat16 g_w_hi[TOPK * EDIM];
__device__ __nv_bfloat16 g_w_lo[TOPK * EDIM];
__device__ __nv_bfloat16 g_ph[(size_t)BATCH * TOPK * MPERB];
__device__ __nv_bfloat16 g_pl[(size_t)BATCH * TOPK * MPERB];
__device__ float g_psum[(size_t)BATCH * TOPK * 512];
__device__ float g_inv[BATCH * TOPK];
__device__ float g_part[(size_t)S3 * BATCH * TOPK * EDIM];

// ---------------- helpers ----------------
__device__ __forceinline__ uint32_t s2u(const void* p) {
    uint32_t a;
    asm("{ .reg .u64 t; cvta.to.shared.u64 t, %1; cvt.u32.u64 %0, t; }" : "=r"(a) : "l"(p));
    return a;
}
__device__ __forceinline__ void cpa16(uint32_t dst, const void* src) {
    asm volatile("cp.async.cg.shared.global [%0], [%1], 16;" :: "r"(dst), "l"(src));
}
#define CP_COMMIT() asm volatile("cp.async.commit_group;")
#define CP_WAIT1()  asm volatile("cp.async.wait_group 1;")

__device__ __forceinline__ void bsplit2(float a, float b, uint32_t& hi, uint32_t& lo) {
    uint32_t h;
    asm("cvt.rn.bf16x2.f32 %0, %1, %2;" : "=r"(h) : "f"(b), "f"(a));
    float ha = __uint_as_float(h << 16);
    float hb = __uint_as_float(h & 0xFFFF0000u);
    float la = a - ha, lb = b - hb;
    asm("cvt.rn.bf16x2.f32 %0, %1, %2;" : "=r"(lo) : "f"(lb), "f"(la));
    hi = h;
}

#define LDSM4(r0, r1, r2, r3, addr) \
    asm volatile("ldmatrix.sync.aligned.m8n8.x4.shared.b16 {%0,%1,%2,%3}, [%4];" \
        : "=r"(r0), "=r"(r1), "=r"(r2), "=r"(r3) : "r"(addr))

#define MMA16816(c0, c1, c2, c3, a0, a1, a2, a3, b0, b1) \
    asm volatile("mma.sync.aligned.m16n8k16.row.col.f32.bf16.bf16.f32 " \
        "{%0,%1,%2,%3},{%4,%5,%6,%7},{%8,%9},{%0,%1,%2,%3};" \
        : "+f"(c0), "+f"(c1), "+f"(c2), "+f"(c3) \
        : "r"(a0), "r"(a1), "r"(a2), "r"(a3), "r"(b0), "r"(b1))

__device__ __forceinline__ void ldsmA(uint32_t A[4][4], uint32_t off) {
    #pragma unroll
    for (int mt = 0; mt < 4; mt++)
        LDSM4(A[mt][0], A[mt][1], A[mt][2], A[mt][3], off + mt * (16 * TROW));
}
__device__ __forceinline__ void ldsmB4(uint32_t B[4][4], uint32_t off) {
    #pragma unroll
    for (int bt = 0; bt < 4; bt++)
        LDSM4(B[bt][0], B[bt][1], B[bt][2], B[bt][3], off + bt * (16 * TROW));
}
__device__ __forceinline__ void mma8(float C[4][8][4], uint32_t A[4][4], uint32_t B[4][4]) {
    #pragma unroll
    for (int mt = 0; mt < 4; mt++)
        #pragma unroll
        for (int nt = 0; nt < 8; nt++)
            MMA16816(C[mt][nt][0], C[mt][nt][1], C[mt][nt][2], C[mt][nt][3],
                     A[mt][0], A[mt][1], A[mt][2], A[mt][3],
                     B[nt >> 1][(nt & 1) * 2], B[nt >> 1][(nt & 1) * 2 + 1]);
}

// ---------------------------------------------------------------------------
// K0w: W fp32 -> bf16 hi/lo
// ---------------------------------------------------------------------------
__global__ __launch_bounds__(256) void k0w(const float* __restrict__ W)
{
    int r = blockIdx.x, t = threadIdx.x;
    size_t gi = (size_t)r * EDIM + t * 2;
    float2 v = *(const float2*)&W[gi];
    uint32_t hi, lo; bsplit2(v.x, v.y, hi, lo);
    ((uint32_t*)g_w_hi)[gi >> 1] = hi;
    ((uint32_t*)g_w_lo)[gi >> 1] = lo;
}

// ---------------------------------------------------------------------------
// K1: s = x.W^T + bias; epilogue: p = exp(s) -> probs hi/lo + per-tile psum
// ---------------------------------------------------------------------------
__global__ __launch_bounds__(256) void k1_gemm(const float* __restrict__ x,
                                               const float* __restrict__ bias)
{
    extern __shared__ char smem[];
    const uint32_t sb = s2u(smem);
    const int tid = threadIdx.x, lane = tid & 31, wid = tid >> 5;
    const int wm = wid & 1, wn = wid >> 1;
    const int m0 = blockIdx.x * 128;
    const int b = m0 >> 16, ml = m0 & 65535;

    const uint32_t a_lane = (wm * 64 + (lane & 15)) * TROW + (lane >> 4) * 16;
    const uint32_t bmat = lane >> 3;
    const uint32_t b_lane = (wn * 64 + (bmat >> 1) * 8 + (lane & 7)) * TROW + (bmat & 1) * 16;

    float C[4][8][4];
    #pragma unroll
    for (int i = 0; i < 4; i++)
        #pragma unroll
        for (int j = 0; j < 8; j++)
            #pragma unroll
            for (int q = 0; q < 4; q++) C[i][j][q] = 0.f;

    const int ar = tid >> 1, ahalf = tid & 1;
    const float* axp = x + (size_t)(m0 + ar) * EDIM + ahalf * 16;
    float4 a4[4];

    auto ldgA = [&](int kb) {
        const float4* p = (const float4*)(axp + kb * 32);
        a4[0] = p[0]; a4[1] = p[1]; a4[2] = p[2]; a4[3] = p[3];
    };
    auto stsA = [&](int s) {
        uint32_t h[8], l[8];
        bsplit2(a4[0].x, a4[0].y, h[0], l[0]); bsplit2(a4[0].z, a4[0].w, h[1], l[1]);
        bsplit2(a4[1].x, a4[1].y, h[2], l[2]); bsplit2(a4[1].z, a4[1].w, h[3], l[3]);
        bsplit2(a4[2].x, a4[2].y, h[4], l[4]); bsplit2(a4[2].z, a4[2].w, h[5], l[5]);
        bsplit2(a4[3].x, a4[3].y, h[6], l[6]); bsplit2(a4[3].z, a4[3].w, h[7], l[7]);
        char* d = smem + K1_A0 + s * K1_ASTG + ar * TROW + ahalf * 32;
        ((uint4*)d)[0] = make_uint4(h[0], h[1], h[2], h[3]);
        ((uint4*)d)[1] = make_uint4(h[4], h[5], h[6], h[7]);
        char* dl = d + 10240;
        ((uint4*)dl)[0] = make_uint4(l[0], l[1], l[2], l[3]);
        ((uint4*)dl)[1] = make_uint4(l[4], l[5], l[6], l[7]);
    };
    auto fillB = [&](int s, int kb) {
        uint32_t st = sb + s * K1_BSTG;
        #pragma unroll
        for (int i = 0; i < 4; i++) {
            int idx = tid + i * 256;
            int r = idx >> 2, c = idx & 3;
            size_t go = ((size_t)r * EDIM + kb * 32) * 2 + c * 16;
            cpa16(st + r * TROW + c * 16, (const char*)g_w_hi + go);
            cpa16(st + 20480 + r * TROW + c * 16, (const char*)g_w_lo + go);
        }
        CP_COMMIT();
    };

    ldgA(0); fillB(0, 0); fillB(1, 1); stsA(0); ldgA(1);

    #pragma unroll 1
    for (int kb = 0; kb < 16; kb++) {
        CP_WAIT1();
        __syncthreads();
        if (kb < 14) fillB((kb + 2) % 3, kb + 2); else CP_COMMIT();
        if (kb < 15) stsA((kb + 1) & 1);
        if (kb < 14) ldgA(kb + 2);
        uint32_t sa = sb + K1_A0 + (kb & 1) * K1_ASTG;
        uint32_t sB = sb + (kb % 3) * K1_BSTG;
        #pragma unroll
        for (int s16 = 0; s16 < 2; s16++) {
            uint32_t Ah[4][4], Al[4][4], Bv[4][4];
            ldsmA(Ah, sa + a_lane + s16 * 32);
            ldsmB4(Bv, sB + b_lane + s16 * 32);
            mma8(C, Ah, Bv);
            ldsmA(Al, sa + 10240 + a_lane + s16 * 32);
            mma8(C, Al, Bv);
            ldsmB4(Bv, sB + 20480 + b_lane + s16 * 32);
            mma8(C, Ah, Bv);
        }
    }
    __syncthreads();

    // epilogue: per 64-n chunk, transpose via smem, exp, psum, bf16-split store
    float* ts = (float*)smem;   // [64 k][132 m]
    #pragma unroll 1
    for (int c = 0; c < 4; c++) {
        if (wn == c) {
            #pragma unroll
            for (int mt = 0; mt < 4; mt++)
                #pragma unroll
                for (int nt = 0; nt < 8; nt++) {
                    int i0 = wm * 64 + mt * 16 + (lane >> 2);
                    int j0 = nt * 8 + (lane & 3) * 2;
                    ts[j0 * 132 + i0]           = C[mt][nt][0];
                    ts[(j0 + 1) * 132 + i0]     = C[mt][nt][1];
                    ts[j0 * 132 + i0 + 8]       = C[mt][nt][2];
                    ts[(j0 + 1) * 132 + i0 + 8] = C[mt][nt][3];
                }
        }
        __syncthreads();
        #pragma unroll
        for (int it = 0; it < 8; it++) {
            int j = it * 8 + wid;
            int kg = c * 64 + j;
            float4 v = *(float4*)&ts[j * 132 + lane * 4];
            float bv = bias[kg];
            v.x = __expf(v.x + bv); v.y = __expf(v.y + bv);
            v.z = __expf(v.z + bv); v.w = __expf(v.w + bv);
            float s = (v.x + v.y) + (v.z + v.w);
            #pragma unroll
            for (int o = 16; o; o >>= 1)
                s += __shfl_xor_sync(0xffffffffu, s, o);
            size_t rowb = (size_t)(b * TOPK + kg);
            if (lane == 0)
                g_psum[rowb * 512 + (ml >> 7)] = s;
            uint2 h, l;
            bsplit2(v.x, v.y, h.x, l.x);
            bsplit2(v.z, v.w, h.y, l.y);
            size_t eo = (rowb * MPERB + ml) * 2 + lane * 8;
            *(uint2*)((char*)g_ph + eo) = h;
            *(uint2*)((char*)g_pl + eo) = l;
        }
        __syncthreads();
    }
}

// ---------------------------------------------------------------------------
// K2a: denom per (b,k) -> 1/denom
// ---------------------------------------------------------------------------
__global__ __launch_bounds__(128) void k2a()
{
    const int row = blockIdx.x, t = threadIdx.x;
    float4 v = ((const float4*)(g_psum + (size_t)row * 512))[t];
    float s = (v.x + v.y) + (v.z + v.w);
    __shared__ float red[128];
    red[t] = s; __syncthreads();
    for (int o = 64; o; o >>= 1) {
        if (t < o) red[t] += red[t + o];
        __syncthreads();
    }
    if (t == 0) g_inv[row] = 1.0f / red[0];
}

// ---------------------------------------------------------------------------
// K3: part[sp][b][k][e] = sum_m probs[k][m] * x[m][e]
//     CTA 128k x 256e, 8 warps (64x64 each). A probs via cp.async,
//     B = x via LDG->split->STS (transposed to e-major in smem).
// ---------------------------------------------------------------------------
__global__ __launch_bounds__(256) void k3_gemm(const float* __restrict__ x)
{
    extern __shared__ char smem[];
    const uint32_t sb = s2u(smem);
    const int tid = threadIdx.x, lane = tid & 31, wid = tid >> 5;
    const int wm = wid & 1, wn = wid >> 1;
    const int kt = blockIdx.x >> 1, et = blockIdx.x & 1;
    const int sp = blockIdx.y, b = blockIdx.z;
    const int k0 = kt * 128, e0 = et * 256;
    const size_t mstart = (size_t)sp * K3M;

    const uint32_t a_lane = (wm * 64 + (lane & 15)) * TROW + (lane >> 4) * 16;
    const uint32_t bmat = lane >> 3;
    const uint32_t b_lane = (wn * 64 + (bmat >> 1) * 8 + (lane & 7)) * TROW + (bmat & 1) * 16;

    float C[4][8][4];
    #pragma unroll
    for (int i = 0; i < 4; i++)
        #pragma unroll
        for (int j = 0; j < 8; j++)
            #pragma unroll
            for (int q = 0; q < 4; q++) C[i][j][q] = 0.f;

    // B prefetch: 2 m-rows x 16 e per thread
    const int m2 = (tid & 15) * 2, eg = tid >> 4;       // eg: 0..15 -> e chunk of 16
    const float* bxp = x + ((size_t)b * MPERB + mstart + m2) * EDIM + e0 + eg * 16;
    float4 b4[8];

    auto ldgB = [&](int kb) {
        const float4* p = (const float4*)(bxp + (size_t)kb * 32 * EDIM);
        b4[0] = p[0]; b4[1] = p[1]; b4[2] = p[2]; b4[3] = p[3];
        const float4* q = (const float4*)((const float*)p + EDIM);
        b4[4] = q[0]; b4[5] = q[1]; b4[6] = q[2]; b4[7] = q[3];
    };
    auto stsB = [&](int s) {
        const float* f0 = (const float*)&b4[0];   // m2 row, 16 e
        const float* f1 = (const float*)&b4[4];   // m2+1 row, 16 e
        char* base = smem + K3_B0 + s * K3_BSTG;
        #pragma unroll
        for (int j = 0; j < 16; j++) {
            uint32_t h, l;
            bsplit2(f0[j], f1[j], h, l);
            *(uint32_t*)(base + (eg * 16 + j) * TROW + m2 * 2) = h;
            *(uint32_t*)(base + 20480 + (eg * 16 + j) * TROW + m2 * 2) = l;
        }
    };
    auto fillA = [&](int s, int kb) {
        uint32_t st = sb + s * K3_ASTG;
        #pragma unroll
        for (int i = 0; i < 2; i++) {
            int idx = tid + i * 256;
            int r = idx >> 2, c = idx & 3;
            size_t go = ((size_t)(b * TOPK + k0 + r) * MPERB + mstart + kb * 32) * 2 + c * 16;
            cpa16(st + r * TROW + c * 16, (const char*)g_ph + go);
            cpa16(st + 10240 + r * TROW + c * 16, (const char*)g_pl + go);
        }
        CP_COMMIT();
    };

    ldgB(0); fillA(0, 0); fillA(1, 1); stsB(0); ldgB(1);

    #pragma unroll 1
    for (int kb = 0; kb < K3M / 32; kb++) {      // 128 stages
        CP_WAIT1();
        __syncthreads();
        if (kb < K3M / 32 - 2) fillA((kb + 2) % 3, kb + 2); else CP_COMMIT();
        if (kb < K3M / 32 - 1) stsB((kb + 1) & 1);
        if (kb < K3M / 32 - 2) ldgB(kb + 2);
        uint32_t sa = sb + (kb % 3) * K3_ASTG;
        uint32_t sB = sb + K3_B0 + (kb & 1) * K3_BSTG;
        #pragma unroll
        for (int s16 = 0; s16 < 2; s16++) {
            uint32_t Ah[4][4], Al[4][4], Bv[4][4];
            ldsmA(Ah, sa + a_lane + s16 * 32);
            ldsmB4(Bv, sB + b_lane + s16 * 32);
            mma8(C, Ah, Bv);
            ldsmA(Al, sa + 10240 + a_lane + s16 * 32);
            mma8(C, Al, Bv);
            ldsmB4(Bv, sB + 20480 + b_lane + s16 * 32);
            mma8(C, Ah, Bv);
        }
    }

    // epilogue: direct [k][e] partial store
    #pragma unroll
    for (int mt = 0; mt < 4; mt++)
        #pragma unroll
        for (int nt = 0; nt < 8; nt++) {
            int i0 = wm * 64 + mt * 16 + (lane >> 2);
            int j0 = wn * 64 + nt * 8 + (lane & 3) * 2;
            float* dst = g_part + ((size_t)(sp * BATCH + b) * TOPK + k0 + i0) * EDIM
                         + e0 + j0;
            float2 v0; v0.x = C[mt][nt][0]; v0.y = C[mt][nt][1];
            float2 v1; v1.x = C[mt][nt][2]; v1.y = C[mt][nt][3];
            *(float2*)dst = v0;
            *(float2*)(dst + (size_t)8 * EDIM) = v1;
        }
}

// ---------------------------------------------------------------------------
// K4: out = inv * sum partials
// ---------------------------------------------------------------------------
__global__ __launch_bounds__(256) void k4_reduce(float* __restrict__ out)
{
    const int idx = blockIdx.x * 256 + threadIdx.x;
    const int b = idx >> 17;
    const int k = (idx >> 9) & 255;
    const int off = idx & 0x1FFFF;
    float s = 0.f;
    #pragma unroll
    for (int sp = 0; sp < S3; sp++)
        s += g_part[((size_t)(sp * BATCH + b) << 17) + off];
    out[idx] = s * g_inv[(b << 8) | k];
}

// ---------------------------------------------------------------------------
extern "C" void kernel_launch(void* const* d_in, const int* in_sizes, int n_in,
                              void* d_out, int out_size)
{
    const float* x    = (const float*)d_in[0];
    const float* W    = (const float*)d_in[1];
    const float* bias = (const float*)d_in[2];
    float* out = (float*)d_out;
    (void)in_sizes; (void)n_in; (void)out_size;

    cudaFuncSetAttribute(k1_gemm, cudaFuncAttributeMaxDynamicSharedMemorySize, SMEM1);
    cudaFuncSetAttribute(k3_gemm, cudaFuncAttributeMaxDynamicSharedMemorySize, SMEM3);

    k0w<<<TOPK, 256>>>(W);
    k1_gemm<<<MTOT / 128, 256, SMEM1>>>(x, bias);
    k2a<<<BATCH * TOPK, 128>>>();
    k3_gemm<<<dim3(4, S3, BATCH), 256, SMEM3>>>(x);
    k4_reduce<<<(BATCH * TOPK * EDIM) / 256, 256>>>(out);
}

// round 12
// speedup vs baseline: 1.1890x; 1.1890x over previous
#include <cuda_runtime.h>
#include <cuda_fp16.h>
#include <cstdint>
#include <math.h>

#define BATCH 2
#define MPERB 65536
#define MTOT  131072
#define EDIM  512
#define TOPK  256
#define S3    16
#define K3M   4096
#define TROW  80

// k1 smem: per stage Ah(10240)+Al(10240)+Bh(20480)+Bl(20480) = 61440, 3 stages
#define K1_STG 61440
#define SMEM1  (3 * K1_STG)      // 184320
// k3 smem: per stage A(20480)+Bh(10240)+Bl(10240) = 40960, 3 stages
#define K3_STG 40960
#define SMEM3  (3 * K3_STG)      // 122880

// ---------------- scratch ----------------
__device__ __half g_w_h[TOPK * EDIM];
__device__ __half g_w_l[TOPK * EDIM];
__device__ __half g_xh[(size_t)MTOT * EDIM];       // [m][e] fp16 hi
__device__ __half g_xl[(size_t)MTOT * EDIM];       // [m][e] fp16 lo
__device__ __half g_xth[(size_t)BATCH * EDIM * MPERB];  // [b][e][m] hi
__device__ __half g_xtl[(size_t)BATCH * EDIM * MPERB];  // [b][e][m] lo
__device__ __half g_p[(size_t)BATCH * TOPK * MPERB];    // probs fp16 [k][m]
__device__ float g_psum[(size_t)BATCH * TOPK * 512];
__device__ float g_inv[BATCH * TOPK];
__device__ float g_part[(size_t)S3 * BATCH * TOPK * EDIM];

// ---------------- helpers ----------------
__device__ __forceinline__ uint32_t s2u(const void* p) {
    uint32_t a;
    asm("{ .reg .u64 t; cvta.to.shared.u64 t, %1; cvt.u32.u64 %0, t; }" : "=r"(a) : "l"(p));
    return a;
}
__device__ __forceinline__ void cpa16(uint32_t dst, const void* src) {
    asm volatile("cp.async.cg.shared.global [%0], [%1], 16;" :: "r"(dst), "l"(src));
}
#define CP_COMMIT() asm volatile("cp.async.commit_group;")
#define CP_WAIT1()  asm volatile("cp.async.wait_group 1;")

// fp16 split: a->low half, b->high half; lo = residuals
__device__ __forceinline__ void fsplit2(float a, float b, uint32_t& hi, uint32_t& lo) {
    __half2 h = __floats2half2_rn(a, b);
    float la = a - __low2float(h);
    float lb = b - __high2float(h);
    __half2 l = __floats2half2_rn(la, lb);
    hi = *reinterpret_cast<uint32_t*>(&h);
    lo = *reinterpret_cast<uint32_t*>(&l);
}

#define LDSM4(r0, r1, r2, r3, addr) \
    asm volatile("ldmatrix.sync.aligned.m8n8.x4.shared.b16 {%0,%1,%2,%3}, [%4];" \
        : "=r"(r0), "=r"(r1), "=r"(r2), "=r"(r3) : "r"(addr))

#define MMA16816(c0, c1, c2, c3, a0, a1, a2, a3, b0, b1) \
    asm volatile("mma.sync.aligned.m16n8k16.row.col.f32.f16.f16.f32 " \
        "{%0,%1,%2,%3},{%4,%5,%6,%7},{%8,%9},{%0,%1,%2,%3};" \
        : "+f"(c0), "+f"(c1), "+f"(c2), "+f"(c3) \
        : "r"(a0), "r"(a1), "r"(a2), "r"(a3), "r"(b0), "r"(b1))

__device__ __forceinline__ void ldsmA(uint32_t A[4][4], uint32_t off) {
    #pragma unroll
    for (int mt = 0; mt < 4; mt++)
        LDSM4(A[mt][0], A[mt][1], A[mt][2], A[mt][3], off + mt * (16 * TROW));
}
__device__ __forceinline__ void ldsmB4(uint32_t B[4][4], uint32_t off) {
    #pragma unroll
    for (int bt = 0; bt < 4; bt++)
        LDSM4(B[bt][0], B[bt][1], B[bt][2], B[bt][3], off + bt * (16 * TROW));
}
__device__ __forceinline__ void mma8(float C[4][8][4], uint32_t A[4][4], uint32_t B[4][4]) {
    #pragma unroll
    for (int mt = 0; mt < 4; mt++)
        #pragma unroll
        for (int nt = 0; nt < 8; nt++)
            MMA16816(C[mt][nt][0], C[mt][nt][1], C[mt][nt][2], C[mt][nt][3],
                     A[mt][0], A[mt][1], A[mt][2], A[mt][3],
                     B[nt >> 1][(nt & 1) * 2], B[nt >> 1][(nt & 1) * 2 + 1]);
}

// ---------------------------------------------------------------------------
// K0x: x fp32 -> fp16 hi/lo in m-major AND e-major layouts (one pass)
// ---------------------------------------------------------------------------
__global__ __launch_bounds__(256) void k0x(const float* __restrict__ x)
{
    __shared__ float t[64][33];
    const int tx = threadIdx.x, ty = threadIdx.y;
    const int m0 = blockIdx.x * 32, e0 = blockIdx.y * 64, b = blockIdx.z;
    const int tid = ty * 32 + tx;
    #pragma unroll
    for (int i = 0; i < 4; i++) {
        int r = ty + 8 * i;
        size_t gi = ((size_t)(b * MPERB + m0 + r)) * EDIM + e0 + tx * 2;
        float2 v = *(const float2*)&x[gi];
        uint32_t hi, lo; fsplit2(v.x, v.y, hi, lo);
        ((uint32_t*)g_xh)[gi >> 1] = hi;
        ((uint32_t*)g_xl)[gi >> 1] = lo;
        t[tx * 2][r] = v.x; t[tx * 2 + 1][r] = v.y;
    }
    __syncthreads();
    #pragma unroll
    for (int i = 0; i < 4; i++) {
        int f = tid + 256 * i;           // 0..1023
        int el = f >> 4, mp = f & 15;
        float v0 = t[el][mp * 2], v1 = t[el][mp * 2 + 1];
        uint32_t hi, lo; fsplit2(v0, v1, hi, lo);
        size_t go = ((size_t)(b * EDIM + e0 + el)) * MPERB + m0;
        ((uint32_t*)g_xth)[(go >> 1) + mp] = hi;
        ((uint32_t*)g_xtl)[(go >> 1) + mp] = lo;
    }
}

// ---------------------------------------------------------------------------
// K0w: W fp32 -> fp16 hi/lo
// ---------------------------------------------------------------------------
__global__ __launch_bounds__(256) void k0w(const float* __restrict__ W)
{
    int r = blockIdx.x, t = threadIdx.x;
    size_t gi = (size_t)r * EDIM + t * 2;
    float2 v = *(const float2*)&W[gi];
    uint32_t hi, lo; fsplit2(v.x, v.y, hi, lo);
    ((uint32_t*)g_w_h)[gi >> 1] = hi;
    ((uint32_t*)g_w_l)[gi >> 1] = lo;
}

// ---------------------------------------------------------------------------
// K1: s = x.W^T + bias; epilogue: p = exp(s) -> fp16 probs + per-tile psum
//     CTA 128m x 256n, 8 warps (64x64). Both operands via cp.async (3-term).
// ---------------------------------------------------------------------------
__global__ __launch_bounds__(256) void k1_gemm(const float* __restrict__ bias)
{
    extern __shared__ char smem[];
    const uint32_t sb = s2u(smem);
    const int tid = threadIdx.x, lane = tid & 31, wid = tid >> 5;
    const int wm = wid & 1, wn = wid >> 1;
    const int m0 = blockIdx.x * 128;
    const int b = m0 >> 16, ml = m0 & 65535;

    const uint32_t a_lane = (wm * 64 + (lane & 15)) * TROW + (lane >> 4) * 16;
    const uint32_t bmat = lane >> 3;
    const uint32_t b_lane = (wn * 64 + (bmat >> 1) * 8 + (lane & 7)) * TROW + (bmat & 1) * 16;

    float C[4][8][4];
    #pragma unroll
    for (int i = 0; i < 4; i++)
        #pragma unroll
        for (int j = 0; j < 8; j++)
            #pragma unroll
            for (int q = 0; q < 4; q++) C[i][j][q] = 0.f;

    auto fill = [&](int s, int kb) {
        uint32_t st = sb + s * K1_STG;
        // A: 128 m-rows x 32 k (hi+lo)
        #pragma unroll
        for (int i = 0; i < 2; i++) {
            int idx = tid + i * 256;
            int r = idx >> 2, c = idx & 3;
            size_t go = ((size_t)(m0 + r) * EDIM + kb * 32) * 2 + c * 16;
            cpa16(st + r * TROW + c * 16, (const char*)g_xh + go);
            cpa16(st + 10240 + r * TROW + c * 16, (const char*)g_xl + go);
        }
        // B: 256 n-rows x 32 k (hi+lo)
        #pragma unroll
        for (int i = 0; i < 4; i++) {
            int idx = tid + i * 256;
            int r = idx >> 2, c = idx & 3;
            size_t go = ((size_t)r * EDIM + kb * 32) * 2 + c * 16;
            cpa16(st + 20480 + r * TROW + c * 16, (const char*)g_w_h + go);
            cpa16(st + 40960 + r * TROW + c * 16, (const char*)g_w_l + go);
        }
        CP_COMMIT();
    };

    fill(0, 0); fill(1, 1);
    #pragma unroll 1
    for (int kb = 0; kb < 16; kb++) {
        CP_WAIT1();
        __syncthreads();
        if (kb < 14) fill((kb + 2) % 3, kb + 2); else CP_COMMIT();
        uint32_t st = sb + (kb % 3) * K1_STG;
        #pragma unroll
        for (int s16 = 0; s16 < 2; s16++) {
            uint32_t Ah[4][4], Al[4][4], Bh[4][4], Bl[4][4];
            ldsmA(Ah, st + a_lane + s16 * 32);
            ldsmA(Al, st + 10240 + a_lane + s16 * 32);
            ldsmB4(Bh, st + 20480 + b_lane + s16 * 32);
            ldsmB4(Bl, st + 40960 + b_lane + s16 * 32);
            mma8(C, Ah, Bh);
            mma8(C, Al, Bh);
            mma8(C, Ah, Bl);
        }
    }
    __syncthreads();

    // epilogue: per 64-n chunk, transpose via smem, exp, psum, fp16 store
    float* ts = (float*)smem;   // [64 k][132 m]
    #pragma unroll 1
    for (int c = 0; c < 4; c++) {
        if (wn == c) {
            #pragma unroll
            for (int mt = 0; mt < 4; mt++)
                #pragma unroll
                for (int nt = 0; nt < 8; nt++) {
                    int i0 = wm * 64 + mt * 16 + (lane >> 2);
                    int j0 = nt * 8 + (lane & 3) * 2;
                    ts[j0 * 132 + i0]           = C[mt][nt][0];
                    ts[(j0 + 1) * 132 + i0]     = C[mt][nt][1];
                    ts[j0 * 132 + i0 + 8]       = C[mt][nt][2];
                    ts[(j0 + 1) * 132 + i0 + 8] = C[mt][nt][3];
                }
        }
        __syncthreads();
        #pragma unroll
        for (int it = 0; it < 8; it++) {
            int j = it * 8 + wid;
            int kg = c * 64 + j;
            float4 v = *(float4*)&ts[j * 132 + lane * 4];
            float bv = bias[kg];
            v.x = __expf(v.x + bv); v.y = __expf(v.y + bv);
            v.z = __expf(v.z + bv); v.w = __expf(v.w + bv);
            float s = (v.x + v.y) + (v.z + v.w);
            #pragma unroll
            for (int o = 16; o; o >>= 1)
                s += __shfl_xor_sync(0xffffffffu, s, o);
            size_t rowb = (size_t)(b * TOPK + kg);
            if (lane == 0)
                g_psum[rowb * 512 + (ml >> 7)] = s;
            __half2 p0 = __floats2half2_rn(v.x, v.y);
            __half2 p1 = __floats2half2_rn(v.z, v.w);
            uint2 hp;
            hp.x = *reinterpret_cast<uint32_t*>(&p0);
            hp.y = *reinterpret_cast<uint32_t*>(&p1);
            *(uint2*)((char*)g_p + (rowb * MPERB + ml + lane * 4) * 2) = hp;
        }
        __syncthreads();
    }
}

// ---------------------------------------------------------------------------
// K2a: denom per (b,k) -> 1/denom
// ---------------------------------------------------------------------------
__global__ __launch_bounds__(128) void k2a()
{
    const int row = blockIdx.x, t = threadIdx.x;
    float4 v = ((const float4*)(g_psum + (size_t)row * 512))[t];
    float s = (v.x + v.y) + (v.z + v.w);
    __shared__ float red[128];
    red[t] = s; __syncthreads();
    for (int o = 64; o; o >>= 1) {
        if (t < o) red[t] += red[t + o];
        __syncthreads();
    }
    if (t == 0) g_inv[row] = 1.0f / red[0];
}

// ---------------------------------------------------------------------------
// K3: part[sp][b][k][e] = sum_m probs[k][m] * x[m][e]
//     CTA 256k x 128e, 8 warps 64x64 (4 k-rows x 2 e-cols). All cp.async.
//     2-term: C += P.Xh + P.Xl (P single fp16).
// ---------------------------------------------------------------------------
__global__ __launch_bounds__(256) void k3_gemm()
{
    extern __shared__ char smem[];
    const uint32_t sb = s2u(smem);
    const int tid = threadIdx.x, lane = tid & 31, wid = tid >> 5;
    const int wm = wid & 3, wn = wid >> 2;
    const int et = blockIdx.x, sp = blockIdx.y, b = blockIdx.z;
    const int e0 = et * 128;
    const size_t mstart = (size_t)sp * K3M;

    const uint32_t a_lane = (wm * 64 + (lane & 15)) * TROW + (lane >> 4) * 16;
    const uint32_t bmat = lane >> 3;
    const uint32_t b_lane = (wn * 64 + (bmat >> 1) * 8 + (lane & 7)) * TROW + (bmat & 1) * 16;

    float C[4][8][4];
    #pragma unroll
    for (int i = 0; i < 4; i++)
        #pragma unroll
        for (int j = 0; j < 8; j++)
            #pragma unroll
            for (int q = 0; q < 4; q++) C[i][j][q] = 0.f;

    auto fill = [&](int s, int kb) {
        uint32_t st = sb + s * K3_STG;
        // A: probs, 256 k-rows x 32 m (single fp16)
        #pragma unroll
        for (int i = 0; i < 4; i++) {
            int idx = tid + i * 256;
            int r = idx >> 2, c = idx & 3;
            size_t go = ((size_t)(b * TOPK + r) * MPERB + mstart + kb * 32) * 2 + c * 16;
            cpa16(st + r * TROW + c * 16, (const char*)g_p + go);
        }
        // B: xT, 128 e-rows x 32 m (hi+lo)
        #pragma unroll
        for (int i = 0; i < 2; i++) {
            int idx = tid + i * 256;
            int r = idx >> 2, c = idx & 3;
            size_t go = ((size_t)(b * EDIM + e0 + r) * MPERB + mstart + kb * 32) * 2 + c * 16;
            cpa16(st + 20480 + r * TROW + c * 16, (const char*)g_xth + go);
            cpa16(st + 30720 + r * TROW + c * 16, (const char*)g_xtl + go);
        }
        CP_COMMIT();
    };

    fill(0, 0); fill(1, 1);
    #pragma unroll 1
    for (int kb = 0; kb < K3M / 32; kb++) {      // 128 stages
        CP_WAIT1();
        __syncthreads();
        if (kb < K3M / 32 - 2) fill((kb + 2) % 3, kb + 2); else CP_COMMIT();
        uint32_t st = sb + (kb % 3) * K3_STG;
        #pragma unroll
        for (int s16 = 0; s16 < 2; s16++) {
            uint32_t Ap[4][4], Bh[4][4], Bl[4][4];
            ldsmA(Ap, st + a_lane + s16 * 32);
            ldsmB4(Bh, st + 20480 + b_lane + s16 * 32);
            ldsmB4(Bl, st + 30720 + b_lane + s16 * 32);
            mma8(C, Ap, Bh);
            mma8(C, Ap, Bl);
        }
    }

    // epilogue: direct [k][e] partial store
    #pragma unroll
    for (int mt = 0; mt < 4; mt++)
        #pragma unroll
        for (int nt = 0; nt < 8; nt++) {
            int i0 = wm * 64 + mt * 16 + (lane >> 2);
            int j0 = wn * 64 + nt * 8 + (lane & 3) * 2;
            float* dst = g_part + ((size_t)(sp * BATCH + b) * TOPK + i0) * EDIM
                         + e0 + j0;
            float2 v0; v0.x = C[mt][nt][0]; v0.y = C[mt][nt][1];
            float2 v1; v1.x = C[mt][nt][2]; v1.y = C[mt][nt][3];
            *(float2*)dst = v0;
            *(float2*)(dst + (size_t)8 * EDIM) = v1;
        }
}

// ---------------------------------------------------------------------------
// K4: out = inv * sum partials
// ---------------------------------------------------------------------------
__global__ __launch_bounds__(256) void k4_reduce(float* __restrict__ out)
{
    const int idx = blockIdx.x * 256 + threadIdx.x;
    const int b = idx >> 17;
    const int k = (idx >> 9) & 255;
    const int off = idx & 0x1FFFF;
    float s = 0.f;
    #pragma unroll
    for (int sp = 0; sp < S3; sp++)
        s += g_part[((size_t)(sp * BATCH + b) << 17) + off];
    out[idx] = s * g_inv[(b << 8) | k];
}

// ---------------------------------------------------------------------------
extern "C" void kernel_launch(void* const* d_in, const int* in_sizes, int n_in,
                              void* d_out, int out_size)
{
    const float* x    = (const float*)d_in[0];
    const float* W    = (const float*)d_in[1];
    const float* bias = (const float*)d_in[2];
    float* out = (float*)d_out;
    (void)in_sizes; (void)n_in; (void)out_size;

    cudaFuncSetAttribute(k1_gemm, cudaFuncAttributeMaxDynamicSharedMemorySize, SMEM1);
    cudaFuncSetAttribute(k3_gemm, cudaFuncAttributeMaxDynamicSharedMemorySize, SMEM3);

    k0x<<<dim3(MPERB / 32, EDIM / 64, BATCH), dim3(32, 8)>>>(x);
    k0w<<<TOPK, 256>>>(W);
    k1_gemm<<<MTOT / 128, 256, SMEM1>>>(bias);
    k2a<<<BATCH * TOPK, 128>>>();
    k3_gemm<<<dim3(4, S3, BATCH), 256, SMEM3>>>();
    k4_reduce<<<(BATCH * TOPK * EDIM) / 256, 256>>>(out);
}

// round 17
// speedup vs baseline: 1.6469x; 1.3850x over previous
#include <cuda_runtime.h>
#include <cuda_fp16.h>
#include <cstdint>
#include <math.h>

#define BATCH 2
#define MPERB 65536
#define MTOT  131072
#define EDIM  512
#define TOPK  256
#define S3    16
#define K3M   4096
#define TROW  80

// k1 smem: per stage Ah(10240)+Al(10240)+Bh(20480) = 40960, 3 stages
#define K1_STG 40960
#define SMEM1  (3 * K1_STG)      // 122880
// k3 smem: per stage A probs(10240)+B xh(10240) = 20480, 3 stages
#define K3_STG 20480
#define SMEM3  (3 * K3_STG)      // 61440  (2 CTAs/SM)

// ---------------- scratch ----------------
__device__ __half g_w_h[TOPK * EDIM];
__device__ __half g_xh[(size_t)MTOT * EDIM];            // [m][e] fp16 hi
__device__ __half g_xl[(size_t)MTOT * EDIM];            // [m][e] fp16 lo
__device__ __half g_xth[(size_t)BATCH * EDIM * MPERB];  // [b][e][m] hi only
__device__ __half g_p[(size_t)BATCH * TOPK * MPERB];    // probs fp16 [k][m]
__device__ float g_psum[(size_t)BATCH * TOPK * 512];
__device__ float g_inv[BATCH * TOPK];
__device__ float g_part[(size_t)S3 * BATCH * TOPK * EDIM];

// ---------------- helpers ----------------
__device__ __forceinline__ uint32_t s2u(const void* p) {
    uint32_t a;
    asm("{ .reg .u64 t; cvta.to.shared.u64 t, %1; cvt.u32.u64 %0, t; }" : "=r"(a) : "l"(p));
    return a;
}
__device__ __forceinline__ void cpa16(uint32_t dst, const void* src) {
    asm volatile("cp.async.cg.shared.global [%0], [%1], 16;" :: "r"(dst), "l"(src));
}
#define CP_COMMIT() asm volatile("cp.async.commit_group;")
#define CP_WAIT1()  asm volatile("cp.async.wait_group 1;")

__device__ __forceinline__ void fsplit2(float a, float b, uint32_t& hi, uint32_t& lo) {
    __half2 h = __floats2half2_rn(a, b);
    float la = a - __low2float(h);
    float lb = b - __high2float(h);
    __half2 l = __floats2half2_rn(la, lb);
    hi = *reinterpret_cast<uint32_t*>(&h);
    lo = *reinterpret_cast<uint32_t*>(&l);
}

#define LDSM4(r0, r1, r2, r3, addr) \
    asm volatile("ldmatrix.sync.aligned.m8n8.x4.shared.b16 {%0,%1,%2,%3}, [%4];" \
        : "=r"(r0), "=r"(r1), "=r"(r2), "=r"(r3) : "r"(addr))

#define MMA16816(c0, c1, c2, c3, a0, a1, a2, a3, b0, b1) \
    asm volatile("mma.sync.aligned.m16n8k16.row.col.f32.f16.f16.f32 " \
        "{%0,%1,%2,%3},{%4,%5,%6,%7},{%8,%9},{%0,%1,%2,%3};" \
        : "+f"(c0), "+f"(c1), "+f"(c2), "+f"(c3) \
        : "r"(a0), "r"(a1), "r"(a2), "r"(a3), "r"(b0), "r"(b1))

__device__ __forceinline__ void ldsmA(uint32_t A[4][4], uint32_t off) {
    #pragma unroll
    for (int mt = 0; mt < 4; mt++)
        LDSM4(A[mt][0], A[mt][1], A[mt][2], A[mt][3], off + mt * (16 * TROW));
}
__device__ __forceinline__ void ldsmB4(uint32_t B[4][4], uint32_t off) {
    #pragma unroll
    for (int bt = 0; bt < 4; bt++)
        LDSM4(B[bt][0], B[bt][1], B[bt][2], B[bt][3], off + bt * (16 * TROW));
}
__device__ __forceinline__ void ldsmB2(uint32_t B[2][4], uint32_t off) {
    #pragma unroll
    for (int bt = 0; bt < 2; bt++)
        LDSM4(B[bt][0], B[bt][1], B[bt][2], B[bt][3], off + bt * (16 * TROW));
}
__device__ __forceinline__ void mma8(float C[4][8][4], uint32_t A[4][4], uint32_t B[4][4]) {
    #pragma unroll
    for (int mt = 0; mt < 4; mt++)
        #pragma unroll
        for (int nt = 0; nt < 8; nt++)
            MMA16816(C[mt][nt][0], C[mt][nt][1], C[mt][nt][2], C[mt][nt][3],
                     A[mt][0], A[mt][1], A[mt][2], A[mt][3],
                     B[nt >> 1][(nt & 1) * 2], B[nt >> 1][(nt & 1) * 2 + 1]);
}
__device__ __forceinline__ void mma4(float C[4][4][4], uint32_t A[4][4], uint32_t B[2][4]) {
    #pragma unroll
    for (int mt = 0; mt < 4; mt++)
        #pragma unroll
        for (int nt = 0; nt < 4; nt++)
            MMA16816(C[mt][nt][0], C[mt][nt][1], C[mt][nt][2], C[mt][nt][3],
                     A[mt][0], A[mt][1], A[mt][2], A[mt][3],
                     B[nt >> 1][(nt & 1) * 2], B[nt >> 1][(nt & 1) * 2 + 1]);
}

// ---------------------------------------------------------------------------
// K0x: x fp32 -> fp16 hi/lo (m-major) AND fp16 hi (e-major) in one pass
// ---------------------------------------------------------------------------
__global__ __launch_bounds__(256) void k0x(const float* __restrict__ x)
{
    __shared__ float t[64][33];
    const int tx = threadIdx.x, ty = threadIdx.y;
    const int m0 = blockIdx.x * 32, e0 = blockIdx.y * 64, b = blockIdx.z;
    const int tid = ty * 32 + tx;
    #pragma unroll
    for (int i = 0; i < 4; i++) {
        int r = ty + 8 * i;
        size_t gi = ((size_t)(b * MPERB + m0 + r)) * EDIM + e0 + tx * 2;
        float2 v = *(const float2*)&x[gi];
        uint32_t hi, lo; fsplit2(v.x, v.y, hi, lo);
        ((uint32_t*)g_xh)[gi >> 1] = hi;
        ((uint32_t*)g_xl)[gi >> 1] = lo;
        t[tx * 2][r] = v.x; t[tx * 2 + 1][r] = v.y;
    }
    __syncthreads();
    #pragma unroll
    for (int i = 0; i < 4; i++) {
        int f = tid + 256 * i;           // 0..1023
        int el = f >> 4, mp = f & 15;
        __half2 h = __floats2half2_rn(t[el][mp * 2], t[el][mp * 2 + 1]);
        size_t go = ((size_t)(b * EDIM + e0 + el)) * MPERB + m0;
        ((uint32_t*)g_xth)[(go >> 1) + mp] = *reinterpret_cast<uint32_t*>(&h);
    }
}

// ---------------------------------------------------------------------------
// K0w: W fp32 -> fp16 hi (2-term k1 only needs Wh)
// ---------------------------------------------------------------------------
__global__ __launch_bounds__(256) void k0w(const float* __restrict__ W)
{
    int r = blockIdx.x, t = threadIdx.x;
    size_t gi = (size_t)r * EDIM + t * 2;
    float2 v = *(const float2*)&W[gi];
    __half2 h = __floats2half2_rn(v.x, v.y);
    ((uint32_t*)g_w_h)[gi >> 1] = *reinterpret_cast<uint32_t*>(&h);
}

// ---------------------------------------------------------------------------
// K1: s = x.Wh^T + bias (exact in x: (xh+xl).Wh); epilogue: p = exp(s)
//     CTA 128m x 256n, 8 warps (64x64). Both operands via cp.async, 2-term.
// ---------------------------------------------------------------------------
__global__ __launch_bounds__(256) void k1_gemm(const float* __restrict__ bias)
{
    extern __shared__ char smem[];
    const uint32_t sb = s2u(smem);
    const int tid = threadIdx.x, lane = tid & 31, wid = tid >> 5;
    const int wm = wid & 1, wn = wid >> 1;
    const int m0 = blockIdx.x * 128;
    const int b = m0 >> 16, ml = m0 & 65535;

    const uint32_t a_lane = (wm * 64 + (lane & 15)) * TROW + (lane >> 4) * 16;
    const uint32_t bmat = lane >> 3;
    const uint32_t b_lane = (wn * 64 + (bmat >> 1) * 8 + (lane & 7)) * TROW + (bmat & 1) * 16;

    float C[4][8][4];
    #pragma unroll
    for (int i = 0; i < 4; i++)
        #pragma unroll
        for (int j = 0; j < 8; j++)
            #pragma unroll
            for (int q = 0; q < 4; q++) C[i][j][q] = 0.f;

    auto fill = [&](int s, int kb) {
        uint32_t st = sb + s * K1_STG;
        #pragma unroll
        for (int i = 0; i < 2; i++) {
            int idx = tid + i * 256;
            int r = idx >> 2, c = idx & 3;
            size_t go = ((size_t)(m0 + r) * EDIM + kb * 32) * 2 + c * 16;
            cpa16(st + r * TROW + c * 16, (const char*)g_xh + go);
            cpa16(st + 10240 + r * TROW + c * 16, (const char*)g_xl + go);
        }
        #pragma unroll
        for (int i = 0; i < 4; i++) {
            int idx = tid + i * 256;
            int r = idx >> 2, c = idx & 3;
            size_t go = ((size_t)r * EDIM + kb * 32) * 2 + c * 16;
            cpa16(st + 20480 + r * TROW + c * 16, (const char*)g_w_h + go);
        }
        CP_COMMIT();
    };

    fill(0, 0); fill(1, 1);
    #pragma unroll 1
    for (int kb = 0; kb < 16; kb++) {
        CP_WAIT1();
        __syncthreads();
        if (kb < 14) fill((kb + 2) % 3, kb + 2); else CP_COMMIT();
        uint32_t st = sb + (kb % 3) * K1_STG;
        #pragma unroll
        for (int s16 = 0; s16 < 2; s16++) {
            uint32_t Ah[4][4], Al[4][4], Bh[4][4];
            ldsmA(Ah, st + a_lane + s16 * 32);
            ldsmA(Al, st + 10240 + a_lane + s16 * 32);
            ldsmB4(Bh, st + 20480 + b_lane + s16 * 32);
            mma8(C, Ah, Bh);
            mma8(C, Al, Bh);
        }
    }
    __syncthreads();

    // epilogue: per 64-n chunk, transpose via smem, exp, psum, fp16 store
    float* ts = (float*)smem;   // [64 k][132 m]
    #pragma unroll 1
    for (int c = 0; c < 4; c++) {
        if (wn == c) {
            #pragma unroll
            for (int mt = 0; mt < 4; mt++)
                #pragma unroll
                for (int nt = 0; nt < 8; nt++) {
                    int i0 = wm * 64 + mt * 16 + (lane >> 2);
                    int j0 = nt * 8 + (lane & 3) * 2;
                    ts[j0 * 132 + i0]           = C[mt][nt][0];
                    ts[(j0 + 1) * 132 + i0]     = C[mt][nt][1];
                    ts[j0 * 132 + i0 + 8]       = C[mt][nt][2];
                    ts[(j0 + 1) * 132 + i0 + 8] = C[mt][nt][3];
                }
        }
        __syncthreads();
        #pragma unroll
        for (int it = 0; it < 8; it++) {
            int j = it * 8 + wid;
            int kg = c * 64 + j;
            float4 v = *(float4*)&ts[j * 132 + lane * 4];
            float bv = bias[kg];
            v.x = __expf(v.x + bv); v.y = __expf(v.y + bv);
            v.z = __expf(v.z + bv); v.w = __expf(v.w + bv);
            float s = (v.x + v.y) + (v.z + v.w);
            #pragma unroll
            for (int o = 16; o; o >>= 1)
                s += __shfl_xor_sync(0xffffffffu, s, o);
            size_t rowb = (size_t)(b * TOPK + kg);
            if (lane == 0)
                g_psum[rowb * 512 + (ml >> 7)] = s;
            __half2 p0 = __floats2half2_rn(v.x, v.y);
            __half2 p1 = __floats2half2_rn(v.z, v.w);
            uint2 hp;
            hp.x = *reinterpret_cast<uint32_t*>(&p0);
            hp.y = *reinterpret_cast<uint32_t*>(&p1);
            *(uint2*)((char*)g_p + (rowb * MPERB + ml + lane * 4) * 2) = hp;
        }
        __syncthreads();
    }
}

// ---------------------------------------------------------------------------
// K2a: denom per (b,k) -> 1/denom
// ---------------------------------------------------------------------------
__global__ __launch_bounds__(128) void k2a()
{
    const int row = blockIdx.x, t = threadIdx.x;
    float4 v = ((const float4*)(g_psum + (size_t)row * 512))[t];
    float s = (v.x + v.y) + (v.z + v.w);
    __shared__ float red[128];
    red[t] = s; __syncthreads();
    for (int o = 64; o; o >>= 1) {
        if (t < o) red[t] += red[t + o];
        __syncthreads();
    }
    if (t == 0) g_inv[row] = 1.0f / red[0];
}

// ---------------------------------------------------------------------------
// K3: part[sp][b][k][e] = sum_m probs[k][m] * xh[m][e]   (1-term)
//     CTA 128k x 128e, 8 warps (64x32). BOTH operands pure cp.async.
//     launch_bounds(256,2): 2 CTAs/SM (smem 61440, regs <=128).
// ---------------------------------------------------------------------------
__global__ __launch_bounds__(256, 2) void k3_gemm()
{
    extern __shared__ char smem[];
    const uint32_t sb = s2u(smem);
    const int tid = threadIdx.x, lane = tid & 31, wid = tid >> 5;
    const int wm = wid & 1, wn = wid >> 1;
    const int kt = blockIdx.x >> 2, et = blockIdx.x & 3;
    const int sp = blockIdx.y, b = blockIdx.z;
    const int k0 = kt * 128, e0 = et * 128;
    const size_t mstart = (size_t)sp * K3M;

    const uint32_t a_lane = (wm * 64 + (lane & 15)) * TROW + (lane >> 4) * 16;
    const uint32_t bmat = lane >> 3;
    const uint32_t b_lane = (wn * 32 + (bmat >> 1) * 8 + (lane & 7)) * TROW + (bmat & 1) * 16;

    float C[4][4][4];
    #pragma unroll
    for (int i = 0; i < 4; i++)
        #pragma unroll
        for (int j = 0; j < 4; j++)
            #pragma unroll
            for (int q = 0; q < 4; q++) C[i][j][q] = 0.f;

    auto fill = [&](int s, int kb) {
        uint32_t st = sb + s * K3_STG;
        // A: probs, 128 k-rows x 32 m
        #pragma unroll
        for (int i = 0; i < 2; i++) {
            int idx = tid + i * 256;
            int r = idx >> 2, c = idx & 3;
            size_t go = ((size_t)(b * TOPK + k0 + r) * MPERB + mstart + kb * 32) * 2 + c * 16;
            cpa16(st + r * TROW + c * 16, (const char*)g_p + go);
        }
        // B: xth e-major, 128 e-rows x 32 m
        #pragma unroll
        for (int i = 0; i < 2; i++) {
            int idx = tid + i * 256;
            int r = idx >> 2, c = idx & 3;
            size_t go = ((size_t)(b * EDIM + e0 + r) * MPERB + mstart + kb * 32) * 2 + c * 16;
            cpa16(st + 10240 + r * TROW + c * 16, (const char*)g_xth + go);
        }
        CP_COMMIT();
    };

    fill(0, 0); fill(1, 1);
    #pragma unroll 1
    for (int kb = 0; kb < K3M / 32; kb++) {      // 128 stages
        CP_WAIT1();
        __syncthreads();
        if (kb < K3M / 32 - 2) fill((kb + 2) % 3, kb + 2); else CP_COMMIT();
        uint32_t st = sb + (kb % 3) * K3_STG;
        #pragma unroll
        for (int s16 = 0; s16 < 2; s16++) {
            uint32_t Ap[4][4], Bv[2][4];
            ldsmA(Ap, st + a_lane + s16 * 32);
            ldsmB2(Bv, st + 10240 + b_lane + s16 * 32);
            mma4(C, Ap, Bv);
        }
    }

    // epilogue: direct [k][e] partial store
    #pragma unroll
    for (int mt = 0; mt < 4; mt++)
        #pragma unroll
        for (int nt = 0; nt < 4; nt++) {
            int i0 = wm * 64 + mt * 16 + (lane >> 2);
            int j0 = wn * 32 + nt * 8 + (lane & 3) * 2;
            float* dst = g_part + ((size_t)(sp * BATCH + b) * TOPK + k0 + i0) * EDIM
                         + e0 + j0;
            float2 v0; v0.x = C[mt][nt][0]; v0.y = C[mt][nt][1];
            float2 v1; v1.x = C[mt][nt][2]; v1.y = C[mt][nt][3];
            *(float2*)dst = v0;
            *(float2*)(dst + (size_t)8 * EDIM) = v1;
        }
}

// ---------------------------------------------------------------------------
// K4: out = inv * sum partials
// ---------------------------------------------------------------------------
__global__ __launch_bounds__(256) void k4_reduce(float* __restrict__ out)
{
    const int idx = blockIdx.x * 256 + threadIdx.x;
    const int b = idx >> 17;
    const int k = (idx >> 9) & 255;
    const int off = idx & 0x1FFFF;
    float s = 0.f;
    #pragma unroll
    for (int sp = 0; sp < S3; sp++)
        s += g_part[((size_t)(sp * BATCH + b) << 17) + off];
    out[idx] = s * g_inv[(b << 8) | k];
}

// ---------------------------------------------------------------------------
extern "C" void kernel_launch(void* const* d_in, const int* in_sizes, int n_in,
                              void* d_out, int out_size)
{
    const float* x    = (const float*)d_in[0];
    const float* W    = (const float*)d_in[1];
    const float* bias = (const float*)d_in[2];
    float* out = (float*)d_out;
    (void)in_sizes; (void)n_in; (void)out_size;

    cudaFuncSetAttribute(k1_gemm, cudaFuncAttributeMaxDynamicSharedMemorySize, SMEM1);
    cudaFuncSetAttribute(k3_gemm, cudaFuncAttributeMaxDynamicSharedMemorySize, SMEM3);

    k0x<<<dim3(MPERB / 32, EDIM / 64, BATCH), dim3(32, 8)>>>(x);
    k0w<<<TOPK, 256>>>(W);
    k1_gemm<<<MTOT / 128, 256, SMEM1>>>(bias);
    k2a<<<BATCH * TOPK, 128>>>();
    k3_gemm<<<dim3(8, S3, BATCH), 256, SMEM3>>>();
    k4_reduce<<<(BATCH * TOPK * EDIM) / 256, 256>>>(out);
}